// round 1
// baseline (speedup 1.0000x reference)
#include <cuda_runtime.h>

// Problem constants (match reference)
#define FB 2
#define FC 256
#define FH 96
#define FW 96
#define FHW (FH * FW)
#define PO 7
#define NBIN 49           // 7*7
#define NROIS 512
#define CG 64             // channel groups of float4 (256/4)
#define ITEMS (NBIN * CG) // 3136 work items per ROI
#define OUT_PER_ROI (FC * NBIN) // 12544 floats

#define SPATIAL_SCALE 0.0625f
#define TRANS_STD 0.1f

// NHWC scratch: [B][H][W][C] floats = 2*96*96*256*4B ≈ 18.9 MB (L2-resident)
__device__ float g_nhwc[FB * FHW * FC];

// ---------------------------------------------------------------------------
// Kernel 1: tiled NCHW -> NHWC transpose (coalesced both sides)
// grid (FHW/32, FC/32, FB), block (32, 8)
// ---------------------------------------------------------------------------
__global__ __launch_bounds__(256) void nchw_to_nhwc_kernel(const float* __restrict__ in) {
    __shared__ float tile[32][33];
    const int b   = blockIdx.z;
    const int hw0 = blockIdx.x * 32;
    const int c0  = blockIdx.y * 32;
    const int tx  = threadIdx.x;
    const int ty  = threadIdx.y;

    const float* src = in + (size_t)b * FC * FHW;
    float* dst = g_nhwc + (size_t)b * FHW * FC;

#pragma unroll
    for (int i = 0; i < 4; i++) {
        int c = c0 + ty + i * 8;
        tile[ty + i * 8][tx] = src[(size_t)c * FHW + hw0 + tx];  // coalesced over hw
    }
    __syncthreads();
#pragma unroll
    for (int i = 0; i < 4; i++) {
        int hw = hw0 + ty + i * 8;
        dst[(size_t)hw * FC + c0 + tx] = tile[tx][ty + i * 8];   // coalesced over c
    }
}

// ---------------------------------------------------------------------------
// Kernel 2: one CTA per ROI.
//   Phase 1: 49 threads compute per-bin sample geometry into smem.
//   Phase 2: 3136 items = (bin, 4-channel group); coalesced float4 gathers
//            from NHWC scratch; results staged into smem output slab.
//   Phase 3: contiguous coalesced writeback of the 12544-float ROI slab.
// ---------------------------------------------------------------------------
__global__ __launch_bounds__(256) void deform_psroi_kernel(
    const float* __restrict__ rois,
    const float* __restrict__ trans,
    float* __restrict__ out)
{
    extern __shared__ float smem[];
    float*  outbuf = smem;                                   // 12544 floats
    float4* wgt    = (float4*)(outbuf + OUT_PER_ROI);        // 196 (bin*4+s)
    int4*   offs   = (int4*)(wgt + 4 * NBIN);                // 196
    float*  invc   = (float*)(offs + 4 * NBIN);              // 49
    __shared__ int sBase;

    const int n   = blockIdx.x;
    const int tid = threadIdx.x;

    // ---- Phase 1: geometry ----
    if (tid < NBIN) {
        const float* r = rois + n * 5;
        // jnp.round == round-half-to-even == rintf
        float x1 = rintf(r[1]) * SPATIAL_SCALE - 0.5f;
        float y1 = rintf(r[2]) * SPATIAL_SCALE - 0.5f;
        float x2 = (rintf(r[3]) + 1.0f) * SPATIAL_SCALE - 0.5f;
        float y2 = (rintf(r[4]) + 1.0f) * SPATIAL_SCALE - 0.5f;
        float rw = fmaxf(x2 - x1, 0.1f);
        float rh = fmaxf(y2 - y1, 0.1f);
        float bw = rw * (1.0f / PO), bh = rh * (1.0f / PO);
        float sw = bw * 0.5f,        sh = bh * 0.5f;

        int ph = tid / PO;
        int pw = tid - ph * PO;
        float tx = trans[((n * 2 + 0) * PO + ph) * PO + pw] * TRANS_STD;
        float ty = trans[((n * 2 + 1) * PO + ph) * PO + pw] * TRANS_STD;
        float wst = pw * bw + x1 + tx * rw;
        float hst = ph * bh + y1 + ty * rh;

        int cnt = 0;
#pragma unroll
        for (int s = 0; s < 4; s++) {
            float w = wst + (float)(s & 1) * sw;
            float h = hst + (float)(s >> 1) * sh;
            bool valid = (w >= -0.5f) && (w <= (float)FW - 0.5f) &&
                         (h >= -0.5f) && (h <= (float)FH - 0.5f);
            float wc = fminf(fmaxf(w, 0.0f), (float)FW - 1.0f);
            float hc = fminf(fmaxf(h, 0.0f), (float)FH - 1.0f);
            float x0f = floorf(wc), y0f = floorf(hc);
            float dx = wc - x0f,    dy = hc - y0f;
            int x0 = (int)x0f,      y0 = (int)y0f;
            int xI = (int)ceilf(wc), yI = (int)ceilf(hc);  // matches jnp.ceil semantics
            float w00 = (1.0f - dx) * (1.0f - dy);
            float w01 = dx * (1.0f - dy);
            float w10 = (1.0f - dx) * dy;
            float w11 = dx * dy;
            if (!valid) { w00 = w01 = w10 = w11 = 0.0f; } else { cnt++; }
            wgt[tid * 4 + s]  = make_float4(w00, w01, w10, w11);
            offs[tid * 4 + s] = make_int4((y0 * FW + x0) * CG,
                                          (y0 * FW + xI) * CG,
                                          (yI * FW + x0) * CG,
                                          (yI * FW + xI) * CG);
        }
        invc[tid] = cnt ? 1.0f / (float)cnt : 0.0f;
        if (tid == 0) sBase = ((int)r[0]) * (FHW * CG);  // batch offset in float4 units
    }
    __syncthreads();

    // ---- Phase 2: gather + blend ----
    const float4* src = (const float4*)g_nhwc;
    const int base = sBase;

    for (int it = tid; it < ITEMS; it += 256) {
        int bin = it >> 6;       // warp-uniform (64 cg per bin)
        int cg  = it & 63;
        float ax = 0.f, ay = 0.f, az = 0.f, aw = 0.f;
#pragma unroll
        for (int s = 0; s < 4; s++) {
            float4 wv = wgt[bin * 4 + s];
            if (wv.x + wv.y + wv.z + wv.w > 0.0f) {   // warp-uniform branch
                int4 o = offs[bin * 4 + s];
                float4 v00 = src[base + o.x + cg];
                float4 v01 = src[base + o.y + cg];
                float4 v10 = src[base + o.z + cg];
                float4 v11 = src[base + o.w + cg];
                ax += wv.x * v00.x + wv.y * v01.x + wv.z * v10.x + wv.w * v11.x;
                ay += wv.x * v00.y + wv.y * v01.y + wv.z * v10.y + wv.w * v11.y;
                az += wv.x * v00.z + wv.y * v01.z + wv.z * v10.z + wv.w * v11.z;
                aw += wv.x * v00.w + wv.y * v01.w + wv.z * v10.w + wv.w * v11.w;
            }
        }
        float ic = invc[bin];
        int c = cg * 4;
        outbuf[(c + 0) * NBIN + bin] = ax * ic;
        outbuf[(c + 1) * NBIN + bin] = ay * ic;
        outbuf[(c + 2) * NBIN + bin] = az * ic;
        outbuf[(c + 3) * NBIN + bin] = aw * ic;
    }
    __syncthreads();

    // ---- Phase 3: coalesced contiguous writeback of the ROI slab ----
    float4* d4 = (float4*)(out + (size_t)n * OUT_PER_ROI);
    const float4* s4 = (const float4*)outbuf;
    for (int i = tid; i < OUT_PER_ROI / 4; i += 256) d4[i] = s4[i];
}

// ---------------------------------------------------------------------------
// Launch
// ---------------------------------------------------------------------------
static const int kPoolSmemBytes =
    OUT_PER_ROI * 4 + 4 * NBIN * 16 + 4 * NBIN * 16 + NBIN * 4;  // 56644

extern "C" void kernel_launch(void* const* d_in, const int* in_sizes, int n_in,
                              void* d_out, int out_size) {
    const float* bottom_data  = (const float*)d_in[0];
    const float* bottom_rois  = (const float*)d_in[1];
    const float* bottom_trans = (const float*)d_in[2];
    float* out = (float*)d_out;

    // >48KB dynamic smem opt-in (idempotent, not a stream op)
    cudaFuncSetAttribute(deform_psroi_kernel,
                         cudaFuncAttributeMaxDynamicSharedMemorySize,
                         kPoolSmemBytes);

    nchw_to_nhwc_kernel<<<dim3(FHW / 32, FC / 32, FB), dim3(32, 8)>>>(bottom_data);
    deform_psroi_kernel<<<NROIS, 256, kPoolSmemBytes>>>(bottom_rois, bottom_trans, out);
}